// round 13
// baseline (speedup 1.0000x reference)
#include <cuda_runtime.h>
#include <cuda_fp16.h>
#include <cstdint>

#define Dd 256
#define HWc 1024
#define Kc 1024
#define NBLK 512
#define NTOT (64 * HWc)
#define CAP2 24
#define CTHR 4e-4f

__device__ float g_cn[Kc];
__device__ float g_zz[NTOT];
__device__ float g_partials[NBLK];
__device__ unsigned int g_done = 0;
__device__ float g_zT[(size_t)NTOT * Dd];   // fp32 m-major z for exact rescore
__device__ __half g_z0[(size_t)NTOT * Dd];  // fp16(z), m-major
__device__ __half g_c0[Kc * Dd];            // fp16(codebook * 8192)

#define SWZ(x) ((x) ^ (((x) >> 3) & 0x70))

// smem offsets (relative to 1024-aligned base)
#define OFF_A    0          // 2 x 16384
#define OFF_B    32768      // 2 x 16384
#define OFF_CN   65536      // 1024 f32
#define OFF_ZZ   69632      // 128 f32
#define OFF_RED  70144      // 256 f32
#define OFF_BI   71168      // 128 i32
#define OFF_CCNT 71680      // 128 i32
#define OFF_CJ   72192      // 128 x 24 i32 = 12288
#define SMEM_BYTES (84480 + 1024)

__device__ __forceinline__ uint32_t smem_u32(const void* p) {
    uint32_t a;
    asm("{ .reg .u64 t; cvta.to.shared.u64 t, %1; cvt.u32.u64 %0, t; }" : "=r"(a) : "l"(p));
    return a;
}

#define LDSM4(r0, r1, r2, r3, addr) \
    asm volatile("ldmatrix.sync.aligned.m8n8.x4.shared.b16 {%0,%1,%2,%3}, [%4];" \
        : "=r"(r0), "=r"(r1), "=r"(r2), "=r"(r3) : "r"(addr))

#define MMA16816(d, a, b) \
    asm volatile("mma.sync.aligned.m16n8k16.row.col.f32.f16.f16.f32 " \
        "{%0,%1,%2,%3},{%4,%5,%6,%7},{%8,%9},{%0,%1,%2,%3};" \
        : "+f"((d)[0]), "+f"((d)[1]), "+f"((d)[2]), "+f"((d)[3]) \
        : "r"((a)[0]), "r"((a)[1]), "r"((a)[2]), "r"((a)[3]), "r"((b)[0]), "r"((b)[1]))

#define CP_ASYNC16(saddr, gptr) \
    asm volatile("cp.async.cg.shared.global [%0], [%1], 16;" \
        :: "r"(saddr), "l"(__cvta_generic_to_global(gptr)))
#define CP_ASYNC16_CA(saddr, gptr) \
    asm volatile("cp.async.ca.shared.global [%0], [%1], 16;" \
        :: "r"(saddr), "l"(__cvta_generic_to_global(gptr)))
#define CP_COMMIT() asm volatile("cp.async.commit_group;")
#define CP_WAIT0()  asm volatile("cp.async.wait_group 0;")

// dist = s - 2*dot, with dot = dotScaled / 8192  =>  s - 2^-12 * dotScaled
#define NEG2_OVER_8192 (-0.000244140625f)

// ---------------------------------------------------------------------------
// prep_all: blocks [0,1024) transpose z (+ zz norms); blocks [1024,2048) codebook
// ---------------------------------------------------------------------------
__global__ __launch_bounds__(256) void prep_all_kernel(const float* __restrict__ z,
                                                       const float* __restrict__ cb) {
    __shared__ float tile[32][65];
    int bb = blockIdx.x;
    int t = threadIdx.x;

    if (bb >= 1024) {
        // ---- codebook part: fp16(cb*8192) + squared norms ----
        float* red = &tile[0][0];
        int k = bb - 1024;
        float v = cb[k * Dd + t];
        g_c0[k * Dd + t] = __float2half_rn(v * 8192.0f);
        red[t] = v * v;
        __syncthreads();
        for (int s = 128; s > 0; s >>= 1) { if (t < s) red[t] += red[t + s]; __syncthreads(); }
        if (t == 0) g_cn[k] = red[0];
        return;
    }

    // ---- z part: transpose to m-major fp32 + fp16, and zz norms ----
    int b = bb >> 4;
    int hw0 = (bb & 15) << 6;
    const float* zb = z + (size_t)b * (Dd * HWc) + hw0;
    size_t mbase = ((size_t)b * HWc + hw0) * Dd;
    float s_lo = 0.f, s_hi = 0.f;   // R1-order zz accumulators (t < 64 only)
    for (int dg = 0; dg < 8; dg++) {
        #pragma unroll
        for (int i = t; i < 32 * 64; i += 256) {
            int d = i >> 6, m = i & 63;
            tile[d][m] = zb[(size_t)(dg * 32 + d) * HWc + m];
        }
        __syncthreads();
        {
            int m = t >> 2, c4 = t & 3;
            __align__(16) __half o0[8];
            __align__(16) float of[8];
            #pragma unroll
            for (int u = 0; u < 8; u++) {
                float v = tile[c4 * 8 + u][m];
                o0[u] = __float2half_rn(v);
                of[u] = v;
            }
            size_t off = mbase + (size_t)m * Dd + dg * 32 + c4 * 8;
            *(uint4*)(g_z0 + off) = *(const uint4*)o0;
            *(float4*)(g_zT + off) = *(const float4*)&of[0];
            *(float4*)(g_zT + off + 4) = *(const float4*)&of[4];
        }
        if (t < 64) {
            // sequential fmaf chain over d ascending — bit-identical to R1 order
            if (dg < 4) {
                #pragma unroll
                for (int u = 0; u < 32; u++) { float v = tile[u][t]; s_lo = fmaf(v, v, s_lo); }
            } else {
                #pragma unroll
                for (int u = 0; u < 32; u++) { float v = tile[u][t]; s_hi = fmaf(v, v, s_hi); }
            }
        }
        __syncthreads();
    }
    if (t < 64) g_zz[(size_t)b * HWc + hw0 + t] = s_lo + s_hi;
}

// ---------------------------------------------------------------------------
// vq: fp16 estimate GEMM (1 sync/stage) + near-min candidates + exact rescore
// grid = 512 CTAs x 256 threads, cp.async double-buffered, occupancy 2
// ---------------------------------------------------------------------------
__global__ __launch_bounds__(256, 2)
void vq_kernel(const float* __restrict__ z, const float* __restrict__ cbf,
               float* __restrict__ out) {
    extern __shared__ char smraw[];
    uint32_t sb = smem_u32(smraw);
    uint32_t ab = (sb + 1023) & ~1023u;
    char* ap = smraw + (ab - sb);

    float* cn_s   = (float*)(ap + OFF_CN);
    float* zz_s   = (float*)(ap + OFF_ZZ);
    float* red    = (float*)(ap + OFF_RED);
    int*   bi_s   = (int*)(ap + OFF_BI);
    int*   ccnt_s = (int*)(ap + OFF_CCNT);
    int*   cj_s   = (int*)(ap + OFF_CJ);

    const int t = threadIdx.x;
    const int wid = t >> 5, lid = t & 31;
    const int mw = wid & 3;        // m-block of 32 rows
    const int nw = wid >> 2;       // n-half of 64 cols
    const int bb = blockIdx.x;
    const int b = bb >> 3;
    const int hw0 = (bb & 7) << 7;
    const int m0 = bb * 128;
    const float* zb = z + ((size_t)b * Dd) * HWc + hw0;

    const uint32_t aB = ab + OFF_A;
    const uint32_t bB = ab + OFF_B;

    // ---- issue stage 0 (A0 + B0, one group) ----
    {
        #pragma unroll
        for (int it = 0; it < 4; it++) {
            int lin = it * 256 + t;
            int row = lin >> 3, u = lin & 7;
            CP_ASYNC16(aB + SWZ(row * 128 + u * 16),
                       g_z0 + (size_t)(m0 + row) * Dd + u * 8);
            CP_ASYNC16_CA(bB + SWZ(row * 128 + u * 16),
                          g_c0 + (size_t)row * Dd + u * 8);
        }
        CP_COMMIT();
    }

    // ---- zz (precomputed), codebook norms, counters ----
    if (t < 128) zz_s[t] = g_zz[(size_t)m0 + t];
    #pragma unroll
    for (int i = 0; i < 4; i++) cn_s[t + i * 256] = g_cn[t + i * 256];
    if (t < 128) ccnt_s[t] = 0;

    // per-thread ldmatrix geometry
    const int g8 = lid & 7, sel = lid >> 3;
    const int aR0 = mw * 32 + (sel & 1) * 8 + g8;
    const int aKo = (sel >> 1) * 16;
    const int bR0 = nw * 64 + (sel >> 1) * 8 + g8;
    const int bKo = (sel & 1) * 16;
    const int lr = lid >> 2, lc2 = (lid & 3) * 2;

    float bestd[2][2];
    #pragma unroll
    for (int i = 0; i < 2; i++)
        #pragma unroll
        for (int j = 0; j < 2; j++) bestd[i][j] = 3.4e38f;

    // first barrier also publishes zz_s/cn_s (combined with stage-0 data barrier below)
    float zz4[4];
    bool zz_loaded = false;

    auto push = [&](int row, int j) {
        int c = atomicAdd(&ccnt_s[row], 1);
        if (c < CAP2) cj_s[row * CAP2 + c] = j;
    };

    for (int nc = 0; nc < 8; nc++) {
        float acc[2][8][4];
        #pragma unroll
        for (int i = 0; i < 2; i++)
            #pragma unroll
            for (int j = 0; j < 8; j++)
                #pragma unroll
                for (int q = 0; q < 4; q++) acc[i][j][q] = 0.f;

        for (int kc = 0; kc < 4; kc++) {
            const int s = nc * 4 + kc;
            CP_WAIT0();
            __syncthreads();          // publishes stage-s data; proves compute(s-1) done
            if (!zz_loaded) {
                zz_loaded = true;
                #pragma unroll
                for (int mt = 0; mt < 2; mt++) {
                    zz4[mt * 2 + 0] = zz_s[mw * 32 + mt * 16 + lr];
                    zz4[mt * 2 + 1] = zz_s[mw * 32 + mt * 16 + lr + 8];
                }
            }
            if (s < 31) {
                int ns = s + 1;
                int nnc = ns >> 2, nkc = ns & 3;
                int col = nkc * 64;
                uint32_t abuf = aB + (ns & 1) * 16384;
                uint32_t bbuf = bB + (ns & 1) * 16384;
                #pragma unroll
                for (int it = 0; it < 4; it++) {
                    int lin = it * 256 + t;
                    int row = lin >> 3, u = lin & 7;
                    CP_ASYNC16(abuf + SWZ(row * 128 + u * 16),
                               g_z0 + (size_t)(m0 + row) * Dd + col + u * 8);
                    CP_ASYNC16_CA(bbuf + SWZ(row * 128 + u * 16),
                                  g_c0 + (size_t)(nnc * 128 + row) * Dd + col + u * 8);
                }
                CP_COMMIT();
            }

            const uint32_t acur = aB + (s & 1) * 16384;
            const uint32_t bcur = bB + (s & 1) * 16384;
            #pragma unroll
            for (int ks = 0; ks < 4; ks++) {
                uint32_t af[2][4];
                #pragma unroll
                for (int mt = 0; mt < 2; mt++) {
                    uint32_t addr = acur + SWZ((aR0 + mt * 16) * 128 + ks * 32 + aKo);
                    LDSM4(af[mt][0], af[mt][1], af[mt][2], af[mt][3], addr);
                }
                uint32_t bf[8][2];
                #pragma unroll
                for (int p = 0; p < 4; p++) {
                    uint32_t addr = bcur + SWZ((bR0 + p * 16) * 128 + ks * 32 + bKo);
                    LDSM4(bf[2 * p][0], bf[2 * p][1], bf[2 * p + 1][0], bf[2 * p + 1][1], addr);
                }
                #pragma unroll
                for (int mt = 0; mt < 2; mt++)
                    #pragma unroll
                    for (int nt = 0; nt < 8; nt++)
                        MMA16816(acc[mt][nt], af[mt], bf[nt]);
            }
        }

        // ---- per-chunk: dists once into regs, quad-min, push near-min ----
        #pragma unroll
        for (int mt = 0; mt < 2; mt++) {
            #pragma unroll
            for (int pr = 0; pr < 2; pr++) {
                const int row = mw * 32 + mt * 16 + pr * 8 + lr;
                const float zzr = zz4[mt * 2 + pr];
                float dv[16];
                float mn = 3.4e38f;
                #pragma unroll
                for (int nt = 0; nt < 8; nt++) {
                    int j = nc * 128 + nw * 64 + nt * 8 + lc2;
                    float2 cn2 = *(const float2*)&cn_s[j];
                    dv[2 * nt]     = fmaf(NEG2_OVER_8192, acc[mt][nt][2 * pr + 0], zzr + cn2.x);
                    dv[2 * nt + 1] = fmaf(NEG2_OVER_8192, acc[mt][nt][2 * pr + 1], zzr + cn2.y);
                    mn = fminf(mn, fminf(dv[2 * nt], dv[2 * nt + 1]));
                }
                mn = fminf(mn, __shfl_xor_sync(0xffffffffu, mn, 1));
                mn = fminf(mn, __shfl_xor_sync(0xffffffffu, mn, 2));
                float merged = fminf(bestd[mt][pr], mn);
                bestd[mt][pr] = merged;
                float pm = merged + CTHR;
                #pragma unroll
                for (int nt = 0; nt < 8; nt++) {
                    int j = nc * 128 + nw * 64 + nt * 8 + lc2;
                    if (dv[2 * nt] < pm) push(row, j);
                    if (dv[2 * nt + 1] < pm) push(row, j + 1);
                }
            }
        }
    }

    __syncthreads();   // publish ccnt_s / cj_s

    // ---- exact rescore of all candidates (R4/R8-proven arithmetic) ----
    if (t < 128) {
        int q = t;
        float zzq = zz_s[q];
        const float* zrow = g_zT + (size_t)(m0 + q) * Dd;
        auto exact = [&](int j) -> float {
            const float* crow = cbf + (size_t)j * Dd;
            float s0 = 0.f, s1 = 0.f, s2 = 0.f, s3 = 0.f;
            #pragma unroll 8
            for (int d = 0; d < Dd; d += 4) {
                float4 c4 = *(const float4*)(crow + d);
                s0 = fmaf(zrow[d + 0], c4.x, s0);
                s1 = fmaf(zrow[d + 1], c4.y, s1);
                s2 = fmaf(zrow[d + 2], c4.z, s2);
                s3 = fmaf(zrow[d + 3], c4.w, s3);
            }
            float dot = (s0 + s1) + (s2 + s3);
            float s = zzq + cn_s[j];
            return fmaf(-2.f, dot, s);
        };
        int cnt = ccnt_s[q];
        float best = 3.4e38f;
        int bi = 0x7fffffff;
        if (cnt > CAP2) {
            // overflow safety net: full exact scan, ascending j, strict <
            bi = 0;
            for (int j = 0; j < Kc; j++) {
                float d = exact(j);
                if (d < best) { best = d; bi = j; }
            }
        } else {
            for (int i = 0; i < cnt; i++) {
                int j = cj_s[q * CAP2 + i];
                float d = exact(j);
                if (d < best || (d == best && j < bi)) { best = d; bi = j; }
            }
        }
        bi_s[q] = bi;
    }
    __syncthreads();

    // ---- outputs: quantized_st + loss partial (R1-proven epilogue) ----
    float* outq = out + ((size_t)b * Dd) * HWc + hw0;
    float lsum = 0.f;
    #pragma unroll 1
    for (int it = 0; it < 32; it++) {
        int lin = it * 256 + t;
        int d = lin >> 5, c4 = lin & 31;
        int mm = 4 * c4;
        float4 zv = *(const float4*)(zb + (size_t)d * HWc + mm);
        float q0 = cbf[(size_t)bi_s[mm + 0] * Dd + d];
        float q1 = cbf[(size_t)bi_s[mm + 1] * Dd + d];
        float q2 = cbf[(size_t)bi_s[mm + 2] * Dd + d];
        float q3 = cbf[(size_t)bi_s[mm + 3] * Dd + d];
        float f0 = q0 - zv.x, f1 = q1 - zv.y, f2 = q2 - zv.z, f3 = q3 - zv.w;
        float4 ov = make_float4(zv.x + f0, zv.y + f1, zv.z + f2, zv.w + f3);
        *(float4*)(outq + (size_t)d * HWc + mm) = ov;
        lsum += f0 * f0 + f1 * f1 + f2 * f2 + f3 * f3;
    }

    if (t < 128) out[16777216 + (size_t)bb * 128 + t] = (float)bi_s[t];

    red[t] = lsum;
    __syncthreads();
    for (int s = 128; s > 0; s >>= 1) { if (t < s) red[t] += red[t + s]; __syncthreads(); }
    if (t == 0) g_partials[bb] = red[0];

    // ---- last-CTA loss reduction ----
    __shared__ unsigned int is_last;
    if (t == 0) {
        __threadfence();
        unsigned int v = atomicAdd(&g_done, 1u);
        is_last = (v == NBLK - 1) ? 1u : 0u;
    }
    __syncthreads();
    if (is_last) {
        red[t] = __ldcg(&g_partials[t]) + __ldcg(&g_partials[t + 256]);
        __syncthreads();
        for (int s = 128; s > 0; s >>= 1) { if (t < s) red[t] += red[t + s]; __syncthreads(); }
        if (t == 0) {
            float S = red[0];
            out[16842752] = S * 0.25f + S;
            g_done = 0;   // reset for next graph replay
        }
    }
}

extern "C" void kernel_launch(void* const* d_in, const int* in_sizes, int n_in,
                              void* d_out, int out_size) {
    const float* z  = (const float*)d_in[0];
    const float* cb = (const float*)d_in[1];
    if (n_in >= 2 && in_sizes[0] == Kc * Dd) {
        z  = (const float*)d_in[1];
        cb = (const float*)d_in[0];
    }
    float* out = (float*)d_out;
    cudaFuncSetAttribute(vq_kernel, cudaFuncAttributeMaxDynamicSharedMemorySize, SMEM_BYTES);
    prep_all_kernel<<<2048, 256>>>(z, cb);
    vq_kernel<<<NBLK, 256, SMEM_BYTES>>>(z, cb, out);
}

// round 14
// speedup vs baseline: 1.7683x; 1.7683x over previous
#include <cuda_runtime.h>
#include <cuda_fp16.h>
#include <cstdint>

#define Dd 256
#define HWc 1024
#define Kc 1024
#define NBLK 512
#define NTOT (64 * HWc)
#define CAP2 24
#define CTHR 4e-4f

__device__ float g_cn[Kc];
__device__ float g_zz[NTOT];
__device__ float g_partials[NBLK];
__device__ unsigned int g_done = 0;
__device__ float g_zT[(size_t)NTOT * Dd];   // fp32 m-major z for exact rescore
__device__ __half g_z0[(size_t)NTOT * Dd];  // fp16(z), m-major
__device__ __half g_c0[Kc * Dd];            // fp16(codebook * 8192)

#define SWZ(x) ((x) ^ (((x) >> 3) & 0x70))

// smem offsets (relative to 1024-aligned base) — R12-proven layout
#define OFF_A    0          // 2 x 16384
#define OFF_B    32768      // 2 x 16384
#define OFF_CN   65536      // 1024 f32
#define OFF_ZZ   69632      // 128 f32
#define OFF_RED  70144      // 256 f32
#define OFF_BD   71168      // 128 f32
#define OFF_BI   71680      // 128 i32
#define OFF_CCNT 72192      // 128 i32
#define OFF_CJ   72704      // 128 x 24 i32
#define OFF_CE   84992      // 128 x 24 f32
#define SMEM_BYTES (97280 + 1024)

__device__ __forceinline__ uint32_t smem_u32(const void* p) {
    uint32_t a;
    asm("{ .reg .u64 t; cvta.to.shared.u64 t, %1; cvt.u32.u64 %0, t; }" : "=r"(a) : "l"(p));
    return a;
}

#define LDSM4(r0, r1, r2, r3, addr) \
    asm volatile("ldmatrix.sync.aligned.m8n8.x4.shared.b16 {%0,%1,%2,%3}, [%4];" \
        : "=r"(r0), "=r"(r1), "=r"(r2), "=r"(r3) : "r"(addr))

#define MMA16816(d, a, b) \
    asm volatile("mma.sync.aligned.m16n8k16.row.col.f32.f16.f16.f32 " \
        "{%0,%1,%2,%3},{%4,%5,%6,%7},{%8,%9},{%0,%1,%2,%3};" \
        : "+f"((d)[0]), "+f"((d)[1]), "+f"((d)[2]), "+f"((d)[3]) \
        : "r"((a)[0]), "r"((a)[1]), "r"((a)[2]), "r"((a)[3]), "r"((b)[0]), "r"((b)[1]))

#define CP_ASYNC16(saddr, gptr) \
    asm volatile("cp.async.cg.shared.global [%0], [%1], 16;" \
        :: "r"(saddr), "l"(__cvta_generic_to_global(gptr)))
#define CP_ASYNC16_CA(saddr, gptr) \
    asm volatile("cp.async.ca.shared.global [%0], [%1], 16;" \
        :: "r"(saddr), "l"(__cvta_generic_to_global(gptr)))
#define CP_COMMIT() asm volatile("cp.async.commit_group;")
#define CP_WAIT1()  asm volatile("cp.async.wait_group 1;")
#define CP_WAIT0()  asm volatile("cp.async.wait_group 0;")

// dist = s - 2*dot, with dot = dotScaled / 8192  =>  s - 2^-12 * dotScaled
#define NEG2_OVER_8192 (-0.000244140625f)

// ---------------------------------------------------------------------------
// prep_all: blocks [0,1024) transpose z (+ zz norms); blocks [1024,2048) codebook
// (R13-proven: zz arithmetic bit-identical to R1 order)
// ---------------------------------------------------------------------------
__global__ __launch_bounds__(256) void prep_all_kernel(const float* __restrict__ z,
                                                       const float* __restrict__ cb) {
    __shared__ float tile[32][65];
    int bb = blockIdx.x;
    int t = threadIdx.x;

    if (bb >= 1024) {
        float* red = &tile[0][0];
        int k = bb - 1024;
        float v = cb[k * Dd + t];
        g_c0[k * Dd + t] = __float2half_rn(v * 8192.0f);
        red[t] = v * v;
        __syncthreads();
        for (int s = 128; s > 0; s >>= 1) { if (t < s) red[t] += red[t + s]; __syncthreads(); }
        if (t == 0) g_cn[k] = red[0];
        return;
    }

    int b = bb >> 4;
    int hw0 = (bb & 15) << 6;
    const float* zb = z + (size_t)b * (Dd * HWc) + hw0;
    size_t mbase = ((size_t)b * HWc + hw0) * Dd;
    float s_lo = 0.f, s_hi = 0.f;   // R1-order zz accumulators (t < 64 only)
    for (int dg = 0; dg < 8; dg++) {
        #pragma unroll
        for (int i = t; i < 32 * 64; i += 256) {
            int d = i >> 6, m = i & 63;
            tile[d][m] = zb[(size_t)(dg * 32 + d) * HWc + m];
        }
        __syncthreads();
        {
            int m = t >> 2, c4 = t & 3;
            __align__(16) __half o0[8];
            __align__(16) float of[8];
            #pragma unroll
            for (int u = 0; u < 8; u++) {
                float v = tile[c4 * 8 + u][m];
                o0[u] = __float2half_rn(v);
                of[u] = v;
            }
            size_t off = mbase + (size_t)m * Dd + dg * 32 + c4 * 8;
            *(uint4*)(g_z0 + off) = *(const uint4*)o0;
            *(float4*)(g_zT + off) = *(const float4*)&of[0];
            *(float4*)(g_zT + off + 4) = *(const float4*)&of[4];
        }
        if (t < 64) {
            if (dg < 4) {
                #pragma unroll
                for (int u = 0; u < 32; u++) { float v = tile[u][t]; s_lo = fmaf(v, v, s_lo); }
            } else {
                #pragma unroll
                for (int u = 0; u < 32; u++) { float v = tile[u][t]; s_hi = fmaf(v, v, s_hi); }
            }
        }
        __syncthreads();
    }
    if (t < 64) g_zz[(size_t)b * HWc + hw0 + t] = s_lo + s_hi;
}

// ---------------------------------------------------------------------------
// vq: single-pass fp16 estimate GEMM (K=256) + near-min candidates + rescore
// grid = 512 CTAs x 256 threads, cp.async double-buffered, occupancy 2
// (R12-proven mainloop; zz read from prep instead of recomputed)
// ---------------------------------------------------------------------------
__global__ __launch_bounds__(256, 2)
void vq_kernel(const float* __restrict__ z, const float* __restrict__ cbf,
               float* __restrict__ out) {
    extern __shared__ char smraw[];
    uint32_t sb = smem_u32(smraw);
    uint32_t ab = (sb + 1023) & ~1023u;
    char* ap = smraw + (ab - sb);

    float* cn_s   = (float*)(ap + OFF_CN);
    float* zz_s   = (float*)(ap + OFF_ZZ);
    float* red    = (float*)(ap + OFF_RED);
    float* bd_s   = (float*)(ap + OFF_BD);
    int*   bi_s   = (int*)(ap + OFF_BI);
    int*   ccnt_s = (int*)(ap + OFF_CCNT);
    int*   cj_s   = (int*)(ap + OFF_CJ);
    float* ce_s   = (float*)(ap + OFF_CE);

    const int t = threadIdx.x;
    const int wid = t >> 5, lid = t & 31;
    const int mw = wid & 3;        // m-block of 32 rows
    const int nw = wid >> 2;       // n-half of 64 cols
    const int bb = blockIdx.x;
    const int b = bb >> 3;
    const int hw0 = (bb & 7) << 7;
    const int m0 = bb * 128;
    const float* zb = z + ((size_t)b * Dd) * HWc + hw0;

    const uint32_t aB = ab + OFF_A;
    const uint32_t bB = ab + OFF_B;

    // ---- issue stage 0 (nc=0, kc=0) ----
    {
        #pragma unroll
        for (int it = 0; it < 4; it++) {
            int lin = it * 256 + t;
            int row = lin >> 3, u = lin & 7;
            CP_ASYNC16(aB + SWZ(row * 128 + u * 16),
                       g_z0 + (size_t)(m0 + row) * Dd + u * 8);
            CP_ASYNC16_CA(bB + SWZ(row * 128 + u * 16),
                          g_c0 + (size_t)row * Dd + u * 8);
        }
        CP_COMMIT();
    }

    // ---- zz (precomputed in prep), codebook norms, counters ----
    if (t < 128) zz_s[t] = g_zz[(size_t)m0 + t];
    #pragma unroll
    for (int i = 0; i < 4; i++) cn_s[t + i * 256] = g_cn[t + i * 256];
    if (t < 128) ccnt_s[t] = 0;
    __syncthreads();

    // per-thread ldmatrix geometry
    const int g8 = lid & 7, sel = lid >> 3;
    const int aR0 = mw * 32 + (sel & 1) * 8 + g8;
    const int aKo = (sel >> 1) * 16;
    const int bR0 = nw * 64 + (sel >> 1) * 8 + g8;
    const int bKo = (sel & 1) * 16;
    const int lr = lid >> 2, lc2 = (lid & 3) * 2;

    float zz4[4];
    #pragma unroll
    for (int mt = 0; mt < 2; mt++) {
        zz4[mt * 2 + 0] = zz_s[mw * 32 + mt * 16 + lr];
        zz4[mt * 2 + 1] = zz_s[mw * 32 + mt * 16 + lr + 8];
    }

    float bestd[2][2];
    int   besti[2][2];
    #pragma unroll
    for (int i = 0; i < 2; i++)
        #pragma unroll
        for (int j = 0; j < 2; j++) { bestd[i][j] = 3.4e38f; besti[i][j] = 0; }

    auto push = [&](int row, int j, float d) {
        int c = atomicAdd(&ccnt_s[row], 1);
        if (c < CAP2) { cj_s[row * CAP2 + c] = j; ce_s[row * CAP2 + c] = d; }
    };

    for (int nc = 0; nc < 8; nc++) {
        float acc[2][8][4];
        #pragma unroll
        for (int i = 0; i < 2; i++)
            #pragma unroll
            for (int j = 0; j < 8; j++)
                #pragma unroll
                for (int q = 0; q < 4; q++) acc[i][j][q] = 0.f;

        for (int kc = 0; kc < 4; kc++) {
            const int s = nc * 4 + kc;
            if (s < 31) {
                int ns = s + 1;
                int nnc = ns >> 2, nkc = ns & 3;
                int col = nkc * 64;
                uint32_t abuf = aB + (ns & 1) * 16384;
                uint32_t bbuf = bB + (ns & 1) * 16384;
                #pragma unroll
                for (int it = 0; it < 4; it++) {
                    int lin = it * 256 + t;
                    int row = lin >> 3, u = lin & 7;
                    CP_ASYNC16(abuf + SWZ(row * 128 + u * 16),
                               g_z0 + (size_t)(m0 + row) * Dd + col + u * 8);
                    CP_ASYNC16_CA(bbuf + SWZ(row * 128 + u * 16),
                                  g_c0 + (size_t)(nnc * 128 + row) * Dd + col + u * 8);
                }
                CP_COMMIT();
                CP_WAIT1();
            } else {
                CP_WAIT0();
            }
            __syncthreads();

            const uint32_t acur = aB + (s & 1) * 16384;
            const uint32_t bcur = bB + (s & 1) * 16384;
            #pragma unroll
            for (int ks = 0; ks < 4; ks++) {
                uint32_t af[2][4];
                #pragma unroll
                for (int mt = 0; mt < 2; mt++) {
                    uint32_t addr = acur + SWZ((aR0 + mt * 16) * 128 + ks * 32 + aKo);
                    LDSM4(af[mt][0], af[mt][1], af[mt][2], af[mt][3], addr);
                }
                uint32_t bf[8][2];
                #pragma unroll
                for (int p = 0; p < 4; p++) {
                    uint32_t addr = bcur + SWZ((bR0 + p * 16) * 128 + ks * 32 + bKo);
                    LDSM4(bf[2 * p][0], bf[2 * p][1], bf[2 * p + 1][0], bf[2 * p + 1][1], addr);
                }
                #pragma unroll
                for (int mt = 0; mt < 2; mt++)
                    #pragma unroll
                    for (int nt = 0; nt < 8; nt++)
                        MMA16816(acc[mt][nt], af[mt], bf[nt]);
            }
            __syncthreads();
        }

        // ---- per-chunk: quad chunk-min first, then push near-min + argmin ----
        #pragma unroll
        for (int mt = 0; mt < 2; mt++) {
            #pragma unroll
            for (int pr = 0; pr < 2; pr++) {
                const int row = mw * 32 + mt * 16 + pr * 8 + lr;
                const float zzr = zz4[mt * 2 + pr];
                float mn = 3.4e38f;
                #pragma unroll
                for (int nt = 0; nt < 8; nt++) {
                    int j = nc * 128 + nw * 64 + nt * 8 + lc2;
                    float2 cn2 = *(const float2*)&cn_s[j];
                    float da = fmaf(NEG2_OVER_8192, acc[mt][nt][2 * pr + 0], zzr + cn2.x);
                    float db = fmaf(NEG2_OVER_8192, acc[mt][nt][2 * pr + 1], zzr + cn2.y);
                    mn = fminf(mn, fminf(da, db));
                }
                mn = fminf(mn, __shfl_xor_sync(0xffffffffu, mn, 1));
                mn = fminf(mn, __shfl_xor_sync(0xffffffffu, mn, 2));
                float merged = fminf(bestd[mt][pr], mn);
                float pm = merged + CTHR;
                #pragma unroll
                for (int nt = 0; nt < 8; nt++) {
                    int j = nc * 128 + nw * 64 + nt * 8 + lc2;
                    float2 cn2 = *(const float2*)&cn_s[j];
                    float da = fmaf(NEG2_OVER_8192, acc[mt][nt][2 * pr + 0], zzr + cn2.x);
                    float db = fmaf(NEG2_OVER_8192, acc[mt][nt][2 * pr + 1], zzr + cn2.y);
                    if (da < pm) push(row, j, da);
                    if (db < pm) push(row, j + 1, db);
                    if (da < bestd[mt][pr]) { bestd[mt][pr] = da; besti[mt][pr] = j; }
                    if (db < bestd[mt][pr]) { bestd[mt][pr] = db; besti[mt][pr] = j + 1; }
                }
            }
        }
    }

    // ---- cross-lane argmin reduce of estimates (per row best_est) ----
    float fd[4];
    int fi[4];
    #pragma unroll
    for (int mt = 0; mt < 2; mt++)
        #pragma unroll
        for (int pr = 0; pr < 2; pr++) {
            float d = bestd[mt][pr];
            int ix = besti[mt][pr];
            #pragma unroll
            for (int w = 1; w <= 2; w <<= 1) {
                float od = __shfl_xor_sync(0xffffffffu, d, w);
                int   oi = __shfl_xor_sync(0xffffffffu, ix, w);
                if (od < d || (od == d && oi < ix)) { d = od; ix = oi; }
            }
            fd[mt * 2 + pr] = d;
            fi[mt * 2 + pr] = ix;
        }
    if (nw == 0 && (lid & 3) == 0) {
        #pragma unroll
        for (int e = 0; e < 4; e++) {
            int row = mw * 32 + (e >> 1) * 16 + (e & 1) * 8 + lr;
            bd_s[row] = fd[e];
            bi_s[row] = fi[e];
        }
    }
    __syncthreads();
    if (nw == 1 && (lid & 3) == 0) {
        #pragma unroll
        for (int e = 0; e < 4; e++) {
            int row = mw * 32 + (e >> 1) * 16 + (e & 1) * 8 + lr;
            float od = bd_s[row];
            int oi = bi_s[row];
            if (fd[e] < od || (fd[e] == od && fi[e] < oi)) {
                bd_s[row] = fd[e];
                bi_s[row] = fi[e];
            }
        }
    }
    __syncthreads();

    // ---- exact rescore of candidates (R4/R8-proven arithmetic) ----
    if (t < 128) {
        int q = t;
        float zzq = zz_s[q];
        const float* zrow = g_zT + (size_t)(m0 + q) * Dd;
        auto exact = [&](int j) -> float {
            const float* crow = cbf + (size_t)j * Dd;
            float s0 = 0.f, s1 = 0.f, s2 = 0.f, s3 = 0.f;
            #pragma unroll 8
            for (int d = 0; d < Dd; d += 4) {
                float4 c4 = *(const float4*)(crow + d);
                s0 = fmaf(zrow[d + 0], c4.x, s0);
                s1 = fmaf(zrow[d + 1], c4.y, s1);
                s2 = fmaf(zrow[d + 2], c4.z, s2);
                s3 = fmaf(zrow[d + 3], c4.w, s3);
            }
            float dot = (s0 + s1) + (s2 + s3);
            float s = zzq + cn_s[j];
            return fmaf(-2.f, dot, s);
        };
        int cnt = ccnt_s[q];
        float best_est = bd_s[q];
        float best = 3.4e38f;
        int bi = 0x7fffffff;
        if (cnt > CAP2) {
            bi = 0;
            for (int j = 0; j < Kc; j++) {
                float d = exact(j);
                if (d < best) { best = d; bi = j; }
            }
        } else {
            for (int i = 0; i < cnt; i++) {
                int j = cj_s[q * CAP2 + i];
                float est = ce_s[q * CAP2 + i];
                if (est < best_est + CTHR) {
                    float d = exact(j);
                    if (d < best || (d == best && j < bi)) { best = d; bi = j; }
                }
            }
        }
        bi_s[q] = bi;
    }
    __syncthreads();

    // ---- outputs: quantized_st + loss partial (R1-proven epilogue) ----
    float* outq = out + ((size_t)b * Dd) * HWc + hw0;
    float lsum = 0.f;
    #pragma unroll 1
    for (int it = 0; it < 32; it++) {
        int lin = it * 256 + t;
        int d = lin >> 5, c4 = lin & 31;
        int mm = 4 * c4;
        float4 zv = *(const float4*)(zb + (size_t)d * HWc + mm);
        float q0 = cbf[(size_t)bi_s[mm + 0] * Dd + d];
        float q1 = cbf[(size_t)bi_s[mm + 1] * Dd + d];
        float q2 = cbf[(size_t)bi_s[mm + 2] * Dd + d];
        float q3 = cbf[(size_t)bi_s[mm + 3] * Dd + d];
        float f0 = q0 - zv.x, f1 = q1 - zv.y, f2 = q2 - zv.z, f3 = q3 - zv.w;
        float4 ov = make_float4(zv.x + f0, zv.y + f1, zv.z + f2, zv.w + f3);
        *(float4*)(outq + (size_t)d * HWc + mm) = ov;
        lsum += f0 * f0 + f1 * f1 + f2 * f2 + f3 * f3;
    }

    if (t < 128) out[16777216 + (size_t)bb * 128 + t] = (float)bi_s[t];

    red[t] = lsum;
    __syncthreads();
    for (int s = 128; s > 0; s >>= 1) { if (t < s) red[t] += red[t + s]; __syncthreads(); }
    if (t == 0) g_partials[bb] = red[0];

    // ---- last-CTA loss reduction ----
    __shared__ unsigned int is_last;
    if (t == 0) {
        __threadfence();
        unsigned int v = atomicAdd(&g_done, 1u);
        is_last = (v == NBLK - 1) ? 1u : 0u;
    }
    __syncthreads();
    if (is_last) {
        red[t] = __ldcg(&g_partials[t]) + __ldcg(&g_partials[t + 256]);
        __syncthreads();
        for (int s = 128; s > 0; s >>= 1) { if (t < s) red[t] += red[t + s]; __syncthreads(); }
        if (t == 0) {
            float S = red[0];
            out[16842752] = S * 0.25f + S;
            g_done = 0;   // reset for next graph replay
        }
    }
}

extern "C" void kernel_launch(void* const* d_in, const int* in_sizes, int n_in,
                              void* d_out, int out_size) {
    const float* z  = (const float*)d_in[0];
    const float* cb = (const float*)d_in[1];
    if (n_in >= 2 && in_sizes[0] == Kc * Dd) {
        z  = (const float*)d_in[1];
        cb = (const float*)d_in[0];
    }
    float* out = (float*)d_out;
    cudaFuncSetAttribute(vq_kernel, cudaFuncAttributeMaxDynamicSharedMemorySize, SMEM_BYTES);
    prep_all_kernel<<<2048, 256>>>(z, cb);
    vq_kernel<<<NBLK, 256, SMEM_BYTES>>>(z, cb, out);
}